// round 11
// baseline (speedup 1.0000x reference)
#include <cuda_runtime.h>
#include <math.h>

#define Bsz 4
#define L 128
#define D 256
#define LN_EPS 1e-5f

// scratch: e-matrices [m][b][i][k], m: 0=e1(QV) 1=e2(VV) 2=e3(QQ) 3=e4(VQ)
__device__ float g_e[4 * Bsz * L * L];

// ------------------------------------------------------------------
// packed f32x2 FMA (sm_100+): d = a*b + d, two fp32 lanes per instr
// ------------------------------------------------------------------
__device__ __forceinline__ void fma2(unsigned long long& d,
                                     unsigned long long a,
                                     unsigned long long b) {
    asm("fma.rn.f32x2 %0, %1, %2, %0;" : "+l"(d) : "l"(a), "l"(b));
}
__device__ __forceinline__ unsigned long long pack2(float x) {
    unsigned long long u = __float_as_uint(x);
    return u | (u << 32);
}
__device__ __forceinline__ float lo32f(unsigned long long u) {
    return __uint_as_float((unsigned)u);
}
__device__ __forceinline__ float hi32f(unsigned long long u) {
    return __uint_as_float((unsigned)(u >> 32));
}

// ------------------------------------------------------------------
// Kernel 1: gram matrices + masked row-max + factored exp
// grid = B*4*8 = 128 CTAs, 256 threads
//   block -> (b, m, i-tile of 16 rows)
//   S[r,k] = X[r,:] . Y[k,:]; e = valid ? exp(0.5*(S - rowmax_valid)) : 0
// ------------------------------------------------------------------
__global__ __launch_bounds__(256, 1)
void gram_exp_kernel(const float* __restrict__ q,
                     const float* __restrict__ v,
                     const int* __restrict__ mask) {
    extern __shared__ float sm1[];
    float* Yt = sm1;                 // transposed Y: [256][129] (padded)
    float* Xs = sm1 + 256 * 129;     // [16][256]
    __shared__ float red[2][4];
    __shared__ int maskS[L];

    int tid = threadIdx.x;
    int bx = blockIdx.x;
    int b = bx >> 5;
    int m = (bx >> 3) & 3;
    int i0 = (bx & 7) * 16;

    const float* X = (m == 0 || m == 2) ? q : v;   // m0:Q m1:V m2:Q m3:V
    const float* Y = (m <= 1) ? v : q;             // m0:V m1:V m2:Q m3:Q
    const float* Xb = X + b * L * D + i0 * D;
    const float* Yb = Y + b * L * D;

    for (int idx = tid; idx < L * D; idx += 256) {
        int k = idx >> 8;
        int d = idx & 255;
        Yt[d * 129 + k] = Yb[idx];
    }
    for (int idx = tid; idx < 16 * D; idx += 256) Xs[idx] = Xb[idx];
    if (tid < L) maskS[tid] = mask[b * L + tid];
    __syncthreads();

    int g = tid >> 7;      // row group (0/1)
    int k = tid & 127;
    for (int rr = 0; rr < 8; rr++) {
        int rl = g * 8 + rr;
        float a0 = 0.f, a1 = 0.f, a2 = 0.f, a3 = 0.f;
        const float* xr = Xs + rl * D;
        const float* yc = Yt + k;
        #pragma unroll 8
        for (int d = 0; d < D; d += 4) {
            a0 += xr[d]     * yc[d * 129];
            a1 += xr[d + 1] * yc[(d + 1) * 129];
            a2 += xr[d + 2] * yc[(d + 2) * 129];
            a3 += xr[d + 3] * yc[(d + 3) * 129];
        }
        float val = (a0 + a1) + (a2 + a3);
        bool valid = (maskS[k] != 0);
        float mx = valid ? val : -INFINITY;
        #pragma unroll
        for (int off = 16; off; off >>= 1)
            mx = fmaxf(mx, __shfl_xor_sync(0xffffffffu, mx, off));
        if ((tid & 31) == 0) red[g][(tid >> 5) & 3] = mx;
        __syncthreads();
        float rowmax = fmaxf(fmaxf(red[g][0], red[g][1]),
                             fmaxf(red[g][2], red[g][3]));
        float e = valid ? expf(0.5f * (val - rowmax)) : 0.f;
        g_e[((m * Bsz + b) * L + (i0 + rl)) * L + k] = e;
        __syncthreads();
    }
}

// ------------------------------------------------------------------
// Kernel 2: per-(b,i,branch) attention-weighted bank contraction.
// grid = B*L*2 = 1024 CTAs (masked-i CTAs exit immediately), 256 threads.
//   smem: bank [128 k][128 d-pairs] as packed f32x2 (128KB)
//         eMat [128 j][128 k]                        (64KB)
//         pS   [128 k][18 j-slots] packed (p,p)      (18KB, padded rows)
//   thread: dp = tid&127 owns fp32 d-pair; jg = tid>>7 owns 8 j's of tile.
//   writes out[b,i,j, h*256 + d] = (sum_k p*bank)/Z   (un-normalized by LN)
// ------------------------------------------------------------------
__global__ __launch_bounds__(256, 1)
void pair_attn_kernel(const float* __restrict__ q,
                      const float* __restrict__ v,
                      const int* __restrict__ mask,
                      float* __restrict__ out) {
    extern __shared__ unsigned char sm2[];
    unsigned long long* bankS = (unsigned long long*)sm2;          // 131072 B
    float* eMatS = (float*)(sm2 + 131072);                         //  65536 B
    unsigned long long* pS = (unsigned long long*)(sm2 + 196608);  //  18432 B
    float* eRowS = (float*)(sm2 + 196608 + 18432);                 //    512 B
    __shared__ float zpart[16][17];
    __shared__ float zS[16];

    int tid = threadIdx.x;
    int bx = blockIdx.x;           // b*256 + i*2 + h
    int h = bx & 1;
    int i = (bx >> 1) & 127;
    int b = bx >> 8;

    if (mask[b * L + i] == 0) return;   // whole i-row zeroed in LN pass

    const float* bank = (h == 0 ? v : q) + b * L * D;
    {   // bank -> smem (layout identical: [k][d], read as f32x2 pairs)
        const float4* src4 = (const float4*)bank;
        float4* dst4 = (float4*)bankS;
        for (int idx = tid; idx < L * D / 4; idx += 256) dst4[idx] = src4[idx];
    }
    {   // e-matrix for this branch (e2 or e4)
        const float4* em4 = (const float4*)(g_e + ((2 * h + 1) * Bsz + b) * L * L);
        float4* emd = (float4*)eMatS;
        for (int idx = tid; idx < L * L / 4; idx += 256) emd[idx] = em4[idx];
    }
    if (tid < L)
        eRowS[tid] = g_e[(((2 * h) * Bsz + b) * L + i) * L + tid];
    __syncthreads();

    int k0 = tid & 127;   // staging-k AND d-pair index
    int jg = tid >> 7;    // j sub-group (0/1) -> 8 j's of 16-tile

    for (int jt = 0; jt < 8; jt++) {
        int j0 = jt * 16;
        if (jt) __syncthreads();   // prior tile's pS/zS consumers done

        // --- stage p[k][jj] = eRow[k]*eMat[j0+jj][k], packed (p,p) ---
        {
            float er = eRowS[k0];
            unsigned long long buf[8];
            #pragma unroll
            for (int qq = 0; qq < 8; qq++) {
                int jj = jg * 8 + qq;
                float p = er * eMatS[(j0 + jj) * L + k0];
                buf[qq] = pack2(p);
            }
            ulonglong2* dst = (ulonglong2*)(pS + k0 * 18 + jg * 8);
            #pragma unroll
            for (int qq = 0; qq < 4; qq++)
                dst[qq] = make_ulonglong2(buf[2 * qq], buf[2 * qq + 1]);
        }
        __syncthreads();

        // --- deterministic Z[jj] = sum_k p[k][jj] ---
        {
            int jj = tid & 15, seg = tid >> 4;
            float s = 0.f;
            #pragma unroll
            for (int kk = 0; kk < 8; kk++)
                s += lo32f(pS[(seg * 8 + kk) * 18 + jj]);
            zpart[jj][seg] = s;
        }
        __syncthreads();
        if (tid < 16) {
            float s = 0.f;
            #pragma unroll
            for (int seg = 0; seg < 16; seg++) s += zpart[tid][seg];
            zS[tid] = s;
        }
        __syncthreads();

        // --- main FFMA2 loop: acc[jj] += p[k][jj] * bank[k][dp] ---
        unsigned long long acc[8];
        #pragma unroll
        for (int qq = 0; qq < 8; qq++) acc[qq] = 0ull;
        const unsigned long long* bk = bankS + k0;   // k0 = d-pair here
        const unsigned long long* pr = pS + jg * 8;
        #pragma unroll 8
        for (int k = 0; k < 128; k++) {
            unsigned long long vv = bk[k * 128];
            const ulonglong2* pp = (const ulonglong2*)(pr + k * 18);
            ulonglong2 p0 = pp[0], p1 = pp[1], p2 = pp[2], p3 = pp[3];
            fma2(acc[0], p0.x, vv);
            fma2(acc[1], p0.y, vv);
            fma2(acc[2], p1.x, vv);
            fma2(acc[3], p1.y, vv);
            fma2(acc[4], p2.x, vv);
            fma2(acc[5], p2.y, vv);
            fma2(acc[6], p3.x, vv);
            fma2(acc[7], p3.y, vv);
        }

        // --- epilogue: divide by Z, store ---
        float* orow = out + (((b * L + i) * L + j0) * 512) + h * 256 + k0 * 2;
        #pragma unroll
        for (int qq = 0; qq < 8; qq++) {
            int jj = jg * 8 + qq;
            float zi = 1.f / zS[jj];
            float2 r;
            r.x = lo32f(acc[qq]) * zi;
            r.y = hi32f(acc[qq]) * zi;
            *(float2*)(orow + jj * 512) = r;
        }
    }
}

// ------------------------------------------------------------------
// Kernel 3: in-place LayerNorm over 512 + affine + i-mask.
// One warp per (b,i,j) row; masked rows just write zeros (never read).
// grid = 65536/8 CTAs, 256 threads.
// ------------------------------------------------------------------
__global__ __launch_bounds__(256, 1)
void ln_mask_kernel(const int* __restrict__ mask,
                    const float* __restrict__ w,
                    const float* __restrict__ bsv,
                    float* __restrict__ out) {
    __shared__ float sw[512], sb[512];
    int tid = threadIdx.x;
    sw[tid] = w[tid];
    sw[tid + 256] = w[tid + 256];
    sb[tid] = bsv[tid];
    sb[tid + 256] = bsv[tid + 256];
    __syncthreads();

    int warp = tid >> 5, lane = tid & 31;
    int row = blockIdx.x * 8 + warp;          // (b*L + i)*L + j
    int b = row >> 14;
    int i = (row >> 7) & 127;
    float4* rp = (float4*)(out + (size_t)row * 512);

    if (mask[b * L + i] == 0) {
        float4 z = make_float4(0.f, 0.f, 0.f, 0.f);
        #pragma unroll
        for (int s = 0; s < 4; s++) rp[s * 32 + lane] = z;
        return;
    }
    float4 x[4];
    float sum = 0.f, sq = 0.f;
    #pragma unroll
    for (int s = 0; s < 4; s++) {
        x[s] = rp[s * 32 + lane];
        sum += x[s].x + x[s].y + x[s].z + x[s].w;
        sq += x[s].x * x[s].x + x[s].y * x[s].y +
              x[s].z * x[s].z + x[s].w * x[s].w;
    }
    #pragma unroll
    for (int off = 16; off; off >>= 1) {
        sum += __shfl_xor_sync(0xffffffffu, sum, off);
        sq  += __shfl_xor_sync(0xffffffffu, sq, off);
    }
    float mu = sum * (1.f / 512.f);
    float var = sq * (1.f / 512.f) - mu * mu;
    float rstd = rsqrtf(var + LN_EPS);
    #pragma unroll
    for (int s = 0; s < 4; s++) {
        int c = (s * 32 + lane) * 4;
        float4 y;
        y.x = (x[s].x - mu) * rstd * sw[c]     + sb[c];
        y.y = (x[s].y - mu) * rstd * sw[c + 1] + sb[c + 1];
        y.z = (x[s].z - mu) * rstd * sw[c + 2] + sb[c + 2];
        y.w = (x[s].w - mu) * rstd * sw[c + 3] + sb[c + 3];
        rp[s * 32 + lane] = y;
    }
}

// ------------------------------------------------------------------
extern "C" void kernel_launch(void* const* d_in, const int* in_sizes, int n_in,
                              void* d_out, int out_size) {
    const float* q   = (const float*)d_in[0];
    const float* v   = (const float*)d_in[1];
    const int*  mask = (const int*)d_in[2];
    const float* w   = (const float*)d_in[3];
    const float* bb  = (const float*)d_in[4];
    float* out = (float*)d_out;

    const int SMEM1 = (256 * 129 + 16 * 256) * 4;                 // 148480
    const int SMEM2 = 131072 + 65536 + 18432 + 512;               // 215552

    cudaFuncSetAttribute(gram_exp_kernel,
                         cudaFuncAttributeMaxDynamicSharedMemorySize, SMEM1);
    cudaFuncSetAttribute(pair_attn_kernel,
                         cudaFuncAttributeMaxDynamicSharedMemorySize, SMEM2);

    gram_exp_kernel<<<Bsz * 4 * 8, 256, SMEM1>>>(q, v, mask);
    pair_attn_kernel<<<Bsz * L * 2, 256, SMEM2>>>(q, v, mask, out);
    ln_mask_kernel<<<(Bsz * L * L) / 8, 256>>>(mask, w, bb, out);
}

// round 14
// speedup vs baseline: 1.0044x; 1.0044x over previous
#include <cuda_runtime.h>
#include <math.h>

#define Bsz 4
#define L 128
#define D 256
#define LN_EPS 1e-5f

// scratch: e-matrices [m][b][i][k], m: 0=e1(QV) 1=e2(VV) 2=e3(QQ) 3=e4(VQ)
__device__ float g_e[4 * Bsz * L * L];

// ------------------------------------------------------------------
// packed f32x2 FMA (sm_100+): d = a*b + d, two fp32 lanes per instr
// ------------------------------------------------------------------
__device__ __forceinline__ void fma2(unsigned long long& d,
                                     unsigned long long a,
                                     unsigned long long b) {
    asm("fma.rn.f32x2 %0, %1, %2, %0;" : "+l"(d) : "l"(a), "l"(b));
}
__device__ __forceinline__ unsigned long long pack2(float x) {
    unsigned long long u = __float_as_uint(x);
    return u | (u << 32);
}
__device__ __forceinline__ float lo32f(unsigned long long u) {
    return __uint_as_float((unsigned)u);
}
__device__ __forceinline__ float hi32f(unsigned long long u) {
    return __uint_as_float((unsigned)(u >> 32));
}

// ------------------------------------------------------------------
// Kernel 1: gram matrices + masked row-max + factored exp
// grid = B*4*8 = 128 CTAs, 256 threads
//   block -> (b, m, i-tile of 16 rows)
//   S[r,k] = X[r,:] . Y[k,:]; e = valid ? exp(0.5*(S - rowmax_valid)) : 0
// ------------------------------------------------------------------
__global__ __launch_bounds__(256, 1)
void gram_exp_kernel(const float* __restrict__ q,
                     const float* __restrict__ v,
                     const int* __restrict__ mask) {
    extern __shared__ float sm1[];
    float* Yt = sm1;                 // transposed Y: [256][129] (padded)
    float* Xs = sm1 + 256 * 129;     // [16][256]
    __shared__ float red[2][4];
    __shared__ int maskS[L];

    int tid = threadIdx.x;
    int bx = blockIdx.x;
    int b = bx >> 5;
    int m = (bx >> 3) & 3;
    int i0 = (bx & 7) * 16;

    const float* X = (m == 0 || m == 2) ? q : v;   // m0:Q m1:V m2:Q m3:V
    const float* Y = (m <= 1) ? v : q;             // m0:V m1:V m2:Q m3:Q
    const float* Xb = X + b * L * D + i0 * D;
    const float* Yb = Y + b * L * D;

    for (int idx = tid; idx < L * D; idx += 256) {
        int k = idx >> 8;
        int d = idx & 255;
        Yt[d * 129 + k] = Yb[idx];
    }
    for (int idx = tid; idx < 16 * D; idx += 256) Xs[idx] = Xb[idx];
    if (tid < L) maskS[tid] = mask[b * L + tid];
    __syncthreads();

    int g = tid >> 7;      // row group (0/1)
    int k = tid & 127;
    for (int rr = 0; rr < 8; rr++) {
        int rl = g * 8 + rr;
        float a0 = 0.f, a1 = 0.f, a2 = 0.f, a3 = 0.f;
        const float* xr = Xs + rl * D;
        const float* yc = Yt + k;
        #pragma unroll 8
        for (int d = 0; d < D; d += 4) {
            a0 += xr[d]     * yc[d * 129];
            a1 += xr[d + 1] * yc[(d + 1) * 129];
            a2 += xr[d + 2] * yc[(d + 2) * 129];
            a3 += xr[d + 3] * yc[(d + 3) * 129];
        }
        float val = (a0 + a1) + (a2 + a3);
        bool valid = (maskS[k] != 0);
        float mx = valid ? val : -INFINITY;
        #pragma unroll
        for (int off = 16; off; off >>= 1)
            mx = fmaxf(mx, __shfl_xor_sync(0xffffffffu, mx, off));
        if ((tid & 31) == 0) red[g][(tid >> 5) & 3] = mx;
        __syncthreads();
        float rowmax = fmaxf(fmaxf(red[g][0], red[g][1]),
                             fmaxf(red[g][2], red[g][3]));
        float e = valid ? expf(0.5f * (val - rowmax)) : 0.f;
        g_e[((m * Bsz + b) * L + (i0 + rl)) * L + k] = e;
        __syncthreads();
    }
}

// ------------------------------------------------------------------
// Kernel 2: per-(b,i,branch) attention-weighted bank contraction.
// grid = B*L*2 = 1024 CTAs (masked-i CTAs exit immediately), 256 threads.
//   smem: bank [128 k][128 d-pairs] as packed f32x2 (128KB)
//         eMat [128 j][128 k]                        (64KB)
//         pS   [128 k][18 j-slots] packed (p,p)      (18KB, padded rows)
//   thread: dp = tid&127 owns fp32 d-pair; jg = tid>>7 owns 8 j's of tile.
//   writes out[b,i,j, h*256 + d] = (sum_k p*bank)/Z   (un-normalized by LN)
// ------------------------------------------------------------------
__global__ __launch_bounds__(256, 1)
void pair_attn_kernel(const float* __restrict__ q,
                      const float* __restrict__ v,
                      const int* __restrict__ mask,
                      float* __restrict__ out) {
    extern __shared__ unsigned char sm2[];
    unsigned long long* bankS = (unsigned long long*)sm2;          // 131072 B
    float* eMatS = (float*)(sm2 + 131072);                         //  65536 B
    unsigned long long* pS = (unsigned long long*)(sm2 + 196608);  //  18432 B
    float* eRowS = (float*)(sm2 + 196608 + 18432);                 //    512 B
    __shared__ float zpart[16][17];
    __shared__ float zS[16];

    int tid = threadIdx.x;
    int bx = blockIdx.x;           // b*256 + i*2 + h
    int h = bx & 1;
    int i = (bx >> 1) & 127;
    int b = bx >> 8;

    if (mask[b * L + i] == 0) return;   // whole i-row zeroed in LN pass

    const float* bank = (h == 0 ? v : q) + b * L * D;
    {   // bank -> smem (layout identical: [k][d], read as f32x2 pairs)
        const float4* src4 = (const float4*)bank;
        float4* dst4 = (float4*)bankS;
        for (int idx = tid; idx < L * D / 4; idx += 256) dst4[idx] = src4[idx];
    }
    {   // e-matrix for this branch (e2 or e4)
        const float4* em4 = (const float4*)(g_e + ((2 * h + 1) * Bsz + b) * L * L);
        float4* emd = (float4*)eMatS;
        for (int idx = tid; idx < L * L / 4; idx += 256) emd[idx] = em4[idx];
    }
    if (tid < L)
        eRowS[tid] = g_e[(((2 * h) * Bsz + b) * L + i) * L + tid];
    __syncthreads();

    int k0 = tid & 127;   // staging-k AND d-pair index
    int jg = tid >> 7;    // j sub-group (0/1) -> 8 j's of 16-tile

    for (int jt = 0; jt < 8; jt++) {
        int j0 = jt * 16;
        if (jt) __syncthreads();   // prior tile's pS/zS consumers done

        // --- stage p[k][jj] = eRow[k]*eMat[j0+jj][k], packed (p,p) ---
        {
            float er = eRowS[k0];
            unsigned long long buf[8];
            #pragma unroll
            for (int qq = 0; qq < 8; qq++) {
                int jj = jg * 8 + qq;
                float p = er * eMatS[(j0 + jj) * L + k0];
                buf[qq] = pack2(p);
            }
            ulonglong2* dst = (ulonglong2*)(pS + k0 * 18 + jg * 8);
            #pragma unroll
            for (int qq = 0; qq < 4; qq++)
                dst[qq] = make_ulonglong2(buf[2 * qq], buf[2 * qq + 1]);
        }
        __syncthreads();

        // --- deterministic Z[jj] = sum_k p[k][jj] ---
        {
            int jj = tid & 15, seg = tid >> 4;
            float s = 0.f;
            #pragma unroll
            for (int kk = 0; kk < 8; kk++)
                s += lo32f(pS[(seg * 8 + kk) * 18 + jj]);
            zpart[jj][seg] = s;
        }
        __syncthreads();
        if (tid < 16) {
            float s = 0.f;
            #pragma unroll
            for (int seg = 0; seg < 16; seg++) s += zpart[tid][seg];
            zS[tid] = s;
        }
        __syncthreads();

        // --- main FFMA2 loop: acc[jj] += p[k][jj] * bank[k][dp] ---
        unsigned long long acc[8];
        #pragma unroll
        for (int qq = 0; qq < 8; qq++) acc[qq] = 0ull;
        const unsigned long long* bk = bankS + k0;   // k0 = d-pair here
        const unsigned long long* pr = pS + jg * 8;
        #pragma unroll 8
        for (int k = 0; k < 128; k++) {
            unsigned long long vv = bk[k * 128];
            const ulonglong2* pp = (const ulonglong2*)(pr + k * 18);
            ulonglong2 p0 = pp[0], p1 = pp[1], p2 = pp[2], p3 = pp[3];
            fma2(acc[0], p0.x, vv);
            fma2(acc[1], p0.y, vv);
            fma2(acc[2], p1.x, vv);
            fma2(acc[3], p1.y, vv);
            fma2(acc[4], p2.x, vv);
            fma2(acc[5], p2.y, vv);
            fma2(acc[6], p3.x, vv);
            fma2(acc[7], p3.y, vv);
        }

        // --- epilogue: divide by Z, store ---
        float* orow = out + (((b * L + i) * L + j0) * 512) + h * 256 + k0 * 2;
        #pragma unroll
        for (int qq = 0; qq < 8; qq++) {
            int jj = jg * 8 + qq;
            float zi = 1.f / zS[jj];
            float2 r;
            r.x = lo32f(acc[qq]) * zi;
            r.y = hi32f(acc[qq]) * zi;
            *(float2*)(orow + jj * 512) = r;
        }
    }
}

// ------------------------------------------------------------------
// Kernel 3: in-place LayerNorm over 512 + affine + i-mask.
// One warp per (b,i,j) row; masked rows just write zeros (never read).
// grid = 65536/8 CTAs, 256 threads.
// ------------------------------------------------------------------
__global__ __launch_bounds__(256, 1)
void ln_mask_kernel(const int* __restrict__ mask,
                    const float* __restrict__ w,
                    const float* __restrict__ bsv,
                    float* __restrict__ out) {
    __shared__ float sw[512], sb[512];
    int tid = threadIdx.x;
    sw[tid] = w[tid];
    sw[tid + 256] = w[tid + 256];
    sb[tid] = bsv[tid];
    sb[tid + 256] = bsv[tid + 256];
    __syncthreads();

    int warp = tid >> 5, lane = tid & 31;
    int row = blockIdx.x * 8 + warp;          // (b*L + i)*L + j
    int b = row >> 14;
    int i = (row >> 7) & 127;
    float4* rp = (float4*)(out + (size_t)row * 512);

    if (mask[b * L + i] == 0) {
        float4 z = make_float4(0.f, 0.f, 0.f, 0.f);
        #pragma unroll
        for (int s = 0; s < 4; s++) rp[s * 32 + lane] = z;
        return;
    }
    float4 x[4];
    float sum = 0.f, sq = 0.f;
    #pragma unroll
    for (int s = 0; s < 4; s++) {
        x[s] = rp[s * 32 + lane];
        sum += x[s].x + x[s].y + x[s].z + x[s].w;
        sq += x[s].x * x[s].x + x[s].y * x[s].y +
              x[s].z * x[s].z + x[s].w * x[s].w;
    }
    #pragma unroll
    for (int off = 16; off; off >>= 1) {
        sum += __shfl_xor_sync(0xffffffffu, sum, off);
        sq  += __shfl_xor_sync(0xffffffffu, sq, off);
    }
    float mu = sum * (1.f / 512.f);
    float var = sq * (1.f / 512.f) - mu * mu;
    float rstd = rsqrtf(var + LN_EPS);
    #pragma unroll
    for (int s = 0; s < 4; s++) {
        int c = (s * 32 + lane) * 4;
        float4 y;
        y.x = (x[s].x - mu) * rstd * sw[c]     + sb[c];
        y.y = (x[s].y - mu) * rstd * sw[c + 1] + sb[c + 1];
        y.z = (x[s].z - mu) * rstd * sw[c + 2] + sb[c + 2];
        y.w = (x[s].w - mu) * rstd * sw[c + 3] + sb[c + 3];
        rp[s * 32 + lane] = y;
    }
}

// ------------------------------------------------------------------
extern "C" void kernel_launch(void* const* d_in, const int* in_sizes, int n_in,
                              void* d_out, int out_size) {
    const float* q   = (const float*)d_in[0];
    const float* v   = (const float*)d_in[1];
    const int*  mask = (const int*)d_in[2];
    const float* w   = (const float*)d_in[3];
    const float* bb  = (const float*)d_in[4];
    float* out = (float*)d_out;

    const int SMEM1 = (256 * 129 + 16 * 256) * 4;                 // 148480
    const int SMEM2 = 131072 + 65536 + 18432 + 512;               // 215552

    cudaFuncSetAttribute(gram_exp_kernel,
                         cudaFuncAttributeMaxDynamicSharedMemorySize, SMEM1);
    cudaFuncSetAttribute(pair_attn_kernel,
                         cudaFuncAttributeMaxDynamicSharedMemorySize, SMEM2);

    gram_exp_kernel<<<Bsz * 4 * 8, 256, SMEM1>>>(q, v, mask);
    pair_attn_kernel<<<Bsz * L * 2, 256, SMEM2>>>(q, v, mask, out);
    ln_mask_kernel<<<(Bsz * L * L) / 8, 256>>>(mask, w, bb, out);
}